// round 4
// baseline (speedup 1.0000x reference)
#include <cuda_runtime.h>
#include <cuda_bf16.h>
#include <cstdint>
#include <cstddef>

#define BB 64
#define TT 2048
#define DD 256
#define VV 256

// ---------------- device scratch (no cudaMalloc allowed) ----------------
__device__ __align__(16) float g_EWx[VV * DD];            // E @ Wx_w^T   [v][e]
__device__ __align__(16) float g_G[VV * DD];              // sigmoid(E @ Wz_w^T) [v][e]
__device__ __align__(16) float g_y[(size_t)BB * TT * DD]; // gated hidden states [b,t,e]

// ---------------- helpers ----------------
__device__ __forceinline__ uint32_t smem_u32(const void* p) {
    uint32_t a;
    asm("{ .reg .u64 t; cvta.to.shared.u64 t, %1; cvt.u32.u64 %0, t; }"
        : "=r"(a) : "l"(p));
    return a;
}

// packed fp32x2 FMA: acc = a*b + acc  (full fp32 precision, 2 MACs / instr)
#define FFMA2(acc, a, b) \
    asm("fma.rn.f32x2 %0, %1, %2, %0;" : "+l"(acc) : "l"(a), "l"(b))

__device__ __forceinline__ float f32x2_hsum4(unsigned long long a,
                                             unsigned long long b) {
    unsigned long long s;
    asm("add.rn.f32x2 %0, %1, %2;" : "=l"(s) : "l"(a), "l"(b));
    float lo, hi;
    asm("mov.b64 {%0, %1}, %2;" : "=f"(lo), "=f"(hi) : "l"(s));
    return lo + hi;
}

__device__ __forceinline__ void mbar_init(uint32_t addr, uint32_t count) {
    asm volatile("mbarrier.init.shared.b64 [%0], %1;" :: "r"(addr), "r"(count)
                 : "memory");
}

// wait with acquire at cluster scope (we consume peer-CTA DSMEM stores)
__device__ __forceinline__ void mbar_wait_cluster(uint32_t addr, uint32_t parity) {
    uint32_t done;
    asm volatile(
        "{\n\t.reg .pred p;\n\t"
        "mbarrier.try_wait.parity.acquire.cluster.shared::cta.b64 p, [%1], %2;\n\t"
        "selp.b32 %0, 1, 0, p;\n\t}"
        : "=r"(done) : "r"(addr), "r"(parity) : "memory");
    if (!done) {
        asm volatile(
            "{\n\t.reg .pred P1;\n\t"
            "W_%=:\n\t"
            "mbarrier.try_wait.parity.acquire.cluster.shared::cta.b64 P1, [%0], %1, 0x989680;\n\t"
            "@P1 bra.uni D_%=;\n\t"
            "bra.uni W_%=;\n\t"
            "D_%=:\n\t}"
            :: "r"(addr), "r"(parity) : "memory");
    }
}

// fast tanh: 1 - 2/(exp(2x)+1); exact limits at +-inf, ~1e-6 rel err
__device__ __forceinline__ float tanh_fast(float x) {
    float e = __expf(2.0f * x);
    return 1.0f - __fdividef(2.0f, e + 1.0f);
}

// ================= Kernel 1: tiny projection tables =================
__global__ __launch_bounds__(256) void proj_kernel(
    const float* __restrict__ E,
    const float* __restrict__ Wx,
    const float* __restrict__ Wz)
{
    __shared__ __align__(16) float4 er[DD / 4];
    const int v = blockIdx.x;
    const int e = threadIdx.x;
    if (e < DD / 4) er[e] = ((const float4*)(E + (size_t)v * DD))[e];
    __syncthreads();

    const float4* wx4 = (const float4*)(Wx + (size_t)e * DD);
    const float4* wz4 = (const float4*)(Wz + (size_t)e * DD);
    float ax0 = 0.f, ax1 = 0.f, az0 = 0.f, az1 = 0.f;
#pragma unroll 8
    for (int i = 0; i < DD / 4; i++) {
        float4 ev = er[i];
        float4 a = wx4[i];
        float4 b = wz4[i];
        ax0 += ev.x * a.x + ev.y * a.y;
        ax1 += ev.z * a.z + ev.w * a.w;
        az0 += ev.x * b.x + ev.y * b.y;
        az1 += ev.z * b.z + ev.w * b.w;
    }
    g_EWx[v * DD + e] = ax0 + ax1;
    g_G[v * DD + e]   = 1.f / (1.f + expf(-(az0 + az1)));
}

// ================= Kernel 2: recurrence =================
// 2-CTA cluster per batch chain (128 clusters, 512 threads each).
// CTA rank r computes outputs eg in [128r, 128r+128). Thread layout:
//   eloc = tid>>2 (output), q = tid&3 (k-slice).
// Each lane's 64 k are split 32 "local" (produced by this CTA) +
// 32 "remote" (produced by peer).
// Per step: phase A = local-half dot (guarded by prev __syncthreads),
// single mbarrier wait (peer posts ONE remote arrive per step after a
// cumulative cluster fence), phase B = remote-half dot, reduce, tanh,
// local store + DSMEM mirror.
// Exit safety: no remote ops at the final step, and a cluster barrier
// before return so no CTA exits while peer traffic is in flight.
#define HP 140   // 128 + 4 pad per 32-chunk (chunks at stride 36 words)

__global__ void __cluster_dims__(2, 1, 1) __launch_bounds__(512, 1)
rnn_kernel(const int* __restrict__ tokens, const float* __restrict__ Wh)
{
    __shared__ int stok[TT];
    __shared__ __align__(16) float hloc[2][HP];   // produced locally
    __shared__ __align__(16) float hrem[2][HP];   // received from peer
    __shared__ __align__(8) unsigned long long mb[2];

    const int tid  = threadIdx.x;
    const int bx   = blockIdx.x;
    const int b    = bx >> 1;
    const int rank = bx & 1;
    const int q    = tid & 3;
    const int eloc = tid >> 2;
    const int eg   = rank * 128 + eloc;

    // ---- weights: 16 f32x2 local-half + 16 f32x2 remote-half ----
    unsigned long long wL[16], wR[16];
    {
        const ulonglong2* sL = (const ulonglong2*)
            (Wh + (size_t)eg * DD + 128 * rank + 32 * q);
        const ulonglong2* sR = (const ulonglong2*)
            (Wh + (size_t)eg * DD + 128 * (rank ^ 1) + 32 * q);
#pragma unroll
        for (int j = 0; j < 8; j++) {
            ulonglong2 a = sL[j];
            wL[2 * j] = a.x; wL[2 * j + 1] = a.y;
            ulonglong2 c = sR[j];
            wR[2 * j] = c.x; wR[2 * j + 1] = c.y;
        }
    }

    for (int i = tid; i < TT; i += 512) stok[i] = tokens[(size_t)b * TT + i];
    if (tid < HP) {
        hloc[0][tid] = 0.f; hloc[1][tid] = 0.f;
        hrem[0][tid] = 0.f; hrem[1][tid] = 0.f;
    }
    if (tid == 0) { mbar_init(smem_u32(&mb[0]), 1); mbar_init(smem_u32(&mb[1]), 1); }

    // cluster barrier: all smem init visible cluster-wide
    asm volatile("barrier.cluster.arrive.aligned;" ::: "memory");
    asm volatile("barrier.cluster.wait.aligned;"   ::: "memory");

    const int jp = eloc + ((eloc >> 5) << 2);       // padded produce index
    // peer addresses
    uint32_t rhrem[2], rmb[2];
    {
        const int peer = rank ^ 1;
        uint32_t l0 = smem_u32(&hrem[0][jp]);
        uint32_t l1 = smem_u32(&hrem[1][jp]);
        uint32_t m0 = smem_u32(&mb[0]);
        uint32_t m1 = smem_u32(&mb[1]);
        asm("mapa.shared::cluster.u32 %0, %1, %2;" : "=r"(rhrem[0]) : "r"(l0), "r"(peer));
        asm("mapa.shared::cluster.u32 %0, %1, %2;" : "=r"(rhrem[1]) : "r"(l1), "r"(peer));
        asm("mapa.shared::cluster.u32 %0, %1, %2;" : "=r"(rmb[0]) : "r"(m0), "r"(peer));
        asm("mapa.shared::cluster.u32 %0, %1, %2;" : "=r"(rmb[1]) : "r"(m1), "r"(peer));
    }
    const uint32_t lmb0 = smem_u32(&mb[0]);
    const uint32_t lmb1 = smem_u32(&mb[1]);

    float* ybase = g_y + (size_t)b * TT * DD;

    // prefetch step-0 gathers
    float wx_n = 0.f, gg_n = 0.f;
    if (q == 0) {
        const int tok0 = stok[0];
        wx_n = __ldg(&g_EWx[tok0 * DD + eg]);
        gg_n = __ldg(&g_G[tok0 * DD + eg]);
    }

    int p = 0;
    uint32_t ph0 = 0, ph1 = 0;

    for (int t = 0; t < TT; t++) {
        const float wx = wx_n, gg = gg_n;
        if (q == 0 && t + 1 < TT) {
            const int tokn = stok[t + 1];
            wx_n = __ldg(&g_EWx[tokn * DD + eg]);
            gg_n = __ldg(&g_G[tokn * DD + eg]);
        }

        // ---- phase A: local-half dot (hloc[p], synced last step) ----
        unsigned long long acc_a = 0ull, acc_b = 0ull;
        {
            const ulonglong2* hb = (const ulonglong2*)(&hloc[p][36 * q]);
#pragma unroll
            for (int i = 0; i < 8; i++) {
                ulonglong2 h2 = hb[i];
                FFMA2(acc_a, wL[2 * i],     h2.x);
                FFMA2(acc_b, wL[2 * i + 1], h2.y);
            }
        }

        // ---- wait for peer's half of h(t-1) ----
        if (t > 0) {
            if (p == 0) { mbar_wait_cluster(lmb0, ph0); ph0 ^= 1; }
            else        { mbar_wait_cluster(lmb1, ph1); ph1 ^= 1; }
        }

        // ---- phase B: remote-half dot ----
        {
            const ulonglong2* hb = (const ulonglong2*)(&hrem[p][36 * q]);
#pragma unroll
            for (int i = 0; i < 8; i++) {
                ulonglong2 h2 = hb[i];
                FFMA2(acc_a, wR[2 * i],     h2.x);
                FFMA2(acc_b, wR[2 * i + 1], h2.y);
            }
        }

        float acc = f32x2_hsum4(acc_a, acc_b);
        acc += __shfl_xor_sync(0xffffffffu, acc, 1);
        acc += __shfl_xor_sync(0xffffffffu, acc, 2);

        const int np = p ^ 1;
        const bool last = (t == TT - 1);
        if (q == 0) {
            const float hn = tanh_fast(acc + wx);
            hloc[np][jp] = hn;
            if (!last) {
                // mirror into peer CTA (consumed at peer's step t+1)
                asm volatile("st.shared::cluster.f32 [%0], %1;"
                             :: "r"(rhrem[np]), "f"(hn) : "memory");
            }
            ybase[(size_t)t * DD + eg] = hn * gg;
        }

        __syncthreads();   // local h(t) visible; orders mirrors before fence

        if (tid == 0 && !last) {
            // make all this CTA's DSMEM mirrors cluster-visible, then signal
            asm volatile("fence.acq_rel.cluster;" ::: "memory");
            asm volatile("mbarrier.arrive.release.cluster.shared::cluster.b64 _, [%0];"
                         :: "r"(rmb[np]) : "memory");
        }
        p = np;
    }

    // exit safety: no CTA may leave while peer-directed traffic is in flight
    asm volatile("barrier.cluster.arrive.aligned;" ::: "memory");
    asm volatile("barrier.cluster.wait.aligned;"   ::: "memory");
}

// ================= Kernel 3: head GEMM =================
// logits[r][v] = sum_d y[r][d] * E[v][d].
// 64x64 tile per CTA, 4x4 micro-tile per thread, f32x2 pairs along k.
#define HKS 68   // 64 + 4 pad

__global__ __launch_bounds__(256) void head_kernel(
    const float* __restrict__ E,
    float* __restrict__ out)
{
    __shared__ __align__(16) float ys[64 * HKS];
    __shared__ __align__(16) float es[64 * HKS];

    const int tid = threadIdx.x;
    const int tx  = tid & 15;     // v-lane: cols tx, tx+16, tx+32, tx+48
    const int ty  = tid >> 4;     // row group: rows ty*4 .. ty*4+3
    const size_t rowbase = (size_t)(blockIdx.x >> 2) * 64;
    const int vbase = (blockIdx.x & 3) * 64;

    unsigned long long acc[4][4];
#pragma unroll
    for (int r = 0; r < 4; r++)
#pragma unroll
        for (int c = 0; c < 4; c++) acc[r][c] = 0ull;

    for (int kc = 0; kc < 4; kc++) {
        const int k0 = kc * 64;
        for (int i = tid; i < 1024; i += 256) {
            const int m = i >> 4, kk = i & 15;
            *(float4*)(ys + m * HKS + kk * 4) =
                *(const float4*)(g_y + (rowbase + m) * DD + k0 + kk * 4);
            *(float4*)(es + m * HKS + kk * 4) =
                *(const float4*)(E + (size_t)(vbase + m) * DD + k0 + kk * 4);
        }
        __syncthreads();

#pragma unroll
        for (int k4 = 0; k4 < 16; k4++) {
            ulonglong2 yv[4], ev[4];
#pragma unroll
            for (int r = 0; r < 4; r++)
                yv[r] = *(const ulonglong2*)(ys + (ty * 4 + r) * HKS + k4 * 4);
#pragma unroll
            for (int c = 0; c < 4; c++)
                ev[c] = *(const ulonglong2*)(es + (tx + 16 * c) * HKS + k4 * 4);
#pragma unroll
            for (int r = 0; r < 4; r++)
#pragma unroll
                for (int c = 0; c < 4; c++) {
                    FFMA2(acc[r][c], yv[r].x, ev[c].x);
                    FFMA2(acc[r][c], yv[r].y, ev[c].y);
                }
        }
        __syncthreads();
    }

#pragma unroll
    for (int r = 0; r < 4; r++) {
        float* orow = out + (rowbase + ty * 4 + r) * VV + vbase;
#pragma unroll
        for (int c = 0; c < 4; c++) {
            float lo, hi;
            asm("mov.b64 {%0, %1}, %2;" : "=f"(lo), "=f"(hi) : "l"(acc[r][c]));
            orow[tx + 16 * c] = lo + hi;
        }
    }
}

// ================= launch =================
extern "C" void kernel_launch(void* const* d_in, const int* in_sizes, int n_in,
                              void* d_out, int out_size)
{
    const int*   tokens = (const int*)  d_in[0];
    const float* E      = (const float*)d_in[1];
    const float* Wx     = (const float*)d_in[2];
    const float* Wh     = (const float*)d_in[3];
    const float* Wz     = (const float*)d_in[4];
    float* out = (float*)d_out;

    proj_kernel<<<VV, 256>>>(E, Wx, Wz);
    rnn_kernel<<<BB * 2, 512>>>(tokens, Wh);
    head_kernel<<<(BB * TT / 64) * (VV / 64), 256>>>(E, out);
}

// round 5
// speedup vs baseline: 1.5045x; 1.5045x over previous
#include <cuda_runtime.h>
#include <cuda_bf16.h>
#include <cstdint>
#include <cstddef>

#define BB 64
#define TT 2048
#define DD 256
#define VV 256
#define QNAN_U 0x7fc00000u

// ---------------- device scratch (no cudaMalloc allowed) ----------------
__device__ __align__(16) float g_EWx[VV * DD];            // E @ Wx_w^T   [v][e]
__device__ __align__(16) float g_G[VV * DD];              // sigmoid(E @ Wz_w^T) [v][e]
__device__ __align__(16) float g_y[(size_t)BB * TT * DD]; // gated hidden states [b,t,e]

// ---------------- helpers ----------------
__device__ __forceinline__ uint32_t smem_u32(const void* p) {
    uint32_t a;
    asm("{ .reg .u64 t; cvta.to.shared.u64 t, %1; cvt.u32.u64 %0, t; }"
        : "=r"(a) : "l"(p));
    return a;
}

// packed fp32x2 FMA: acc = a*b + acc  (full fp32 precision, 2 MACs / instr)
#define FFMA2(acc, a, b) \
    asm("fma.rn.f32x2 %0, %1, %2, %0;" : "+l"(acc) : "l"(a), "l"(b))

__device__ __forceinline__ float f32x2_hsum4(unsigned long long a,
                                             unsigned long long b) {
    unsigned long long s;
    asm("add.rn.f32x2 %0, %1, %2;" : "=l"(s) : "l"(a), "l"(b));
    float lo, hi;
    asm("mov.b64 {%0, %1}, %2;" : "=f"(lo), "=f"(hi) : "l"(s));
    return lo + hi;
}

// fast tanh: 1 - 2/(exp(2x)+1); exact limits at +-inf, ~1e-6 rel err, never NaN
__device__ __forceinline__ float tanh_fast(float x) {
    float e = __expf(2.0f * x);
    return 1.0f - __fdividef(2.0f, e + 1.0f);
}

// ================= Kernel 1: tiny projection tables =================
__global__ __launch_bounds__(256) void proj_kernel(
    const float* __restrict__ E,
    const float* __restrict__ Wx,
    const float* __restrict__ Wz)
{
    __shared__ __align__(16) float4 er[DD / 4];
    const int v = blockIdx.x;
    const int e = threadIdx.x;
    if (e < DD / 4) er[e] = ((const float4*)(E + (size_t)v * DD))[e];
    __syncthreads();

    const float4* wx4 = (const float4*)(Wx + (size_t)e * DD);
    const float4* wz4 = (const float4*)(Wz + (size_t)e * DD);
    float ax0 = 0.f, ax1 = 0.f, az0 = 0.f, az1 = 0.f;
#pragma unroll 8
    for (int i = 0; i < DD / 4; i++) {
        float4 ev = er[i];
        float4 a = wx4[i];
        float4 b = wz4[i];
        ax0 += ev.x * a.x + ev.y * a.y;
        ax1 += ev.z * a.z + ev.w * a.w;
        az0 += ev.x * b.x + ev.y * b.y;
        az1 += ev.z * b.z + ev.w * b.w;
    }
    g_EWx[v * DD + e] = ax0 + ax1;
    g_G[v * DD + e]   = 1.f / (1.f + expf(-(az0 + az1)));
}

// ================= Kernel 2: recurrence =================
// 2-CTA cluster per batch chain (128 clusters, 512 threads each).
// CTA rank r computes outputs eg in [128r, 128r+128).
//   eloc = tid>>2 (output), q = tid&3 (k-slice of 64: 32 local + 32 remote).
// Synchronization: DATA-AS-FLAG. h values are tanh outputs (never NaN).
// hrem buffers hold qNaN sentinels; peer publishes via plain weak
// st.shared::cluster; consumer volatile-loads + FMAs and retries while the
// partial sum is NaN. NO cluster fences / mbarriers / releases in the loop.
// Buffer lifecycle (parity p at step t): consumed at t, reset to qNaN between
// the two __syncthreads of step t, rewritten by peer only after it consumed
// our step-t publish (two fabric crossings + peer compute of margin).
#define HP 140   // 128 + 4 pad per 32-chunk (chunks at stride 36 words)

__global__ void __cluster_dims__(2, 1, 1) __launch_bounds__(512, 1)
rnn_kernel(const int* __restrict__ tokens, const float* __restrict__ Wh)
{
    __shared__ int stok[TT];
    __shared__ __align__(16) float hloc[2][HP];   // produced locally
    __shared__ __align__(16) float hrem[2][HP];   // received from peer

    const int tid  = threadIdx.x;
    const int bx   = blockIdx.x;
    const int b    = bx >> 1;
    const int rank = bx & 1;
    const int q    = tid & 3;
    const int eloc = tid >> 2;
    const int eg   = rank * 128 + eloc;

    // ---- weights: 16 f32x2 local-half + 16 f32x2 remote-half ----
    unsigned long long wL[16], wR[16];
    {
        const ulonglong2* sL = (const ulonglong2*)
            (Wh + (size_t)eg * DD + 128 * rank + 32 * q);
        const ulonglong2* sR = (const ulonglong2*)
            (Wh + (size_t)eg * DD + 128 * (rank ^ 1) + 32 * q);
#pragma unroll
        for (int j = 0; j < 8; j++) {
            ulonglong2 a = sL[j];
            wL[2 * j] = a.x; wL[2 * j + 1] = a.y;
            ulonglong2 c = sR[j];
            wR[2 * j] = c.x; wR[2 * j + 1] = c.y;
        }
    }

    for (int i = tid; i < TT; i += 512) stok[i] = tokens[(size_t)b * TT + i];
    if (tid < HP) {
        hloc[0][tid] = 0.f;            // h0 = 0
        hloc[1][tid] = 0.f;
        hrem[0][tid] = 0.f;            // step 0 consumes zeros (valid)
        ((unsigned int*)hrem[1])[tid] = QNAN_U;  // step 1 gated on peer publish
    }

    // cluster barrier: all smem init visible before any peer traffic
    asm volatile("barrier.cluster.arrive.aligned;" ::: "memory");
    asm volatile("barrier.cluster.wait.aligned;"   ::: "memory");

    const int jp = eloc + ((eloc >> 5) << 2);       // padded produce index
    // peer addresses for DSMEM mirrors (both parities)
    uint32_t rhrem[2];
    {
        const int peer = rank ^ 1;
        uint32_t l0 = smem_u32(&hrem[0][jp]);
        uint32_t l1 = smem_u32(&hrem[1][jp]);
        asm("mapa.shared::cluster.u32 %0, %1, %2;" : "=r"(rhrem[0]) : "r"(l0), "r"(peer));
        asm("mapa.shared::cluster.u32 %0, %1, %2;" : "=r"(rhrem[1]) : "r"(l1), "r"(peer));
    }
    // poll base addresses (this thread's 32 remote-half words)
    uint32_t pollAddr[2];
    pollAddr[0] = smem_u32(&hrem[0][36 * q]);
    pollAddr[1] = smem_u32(&hrem[1][36 * q]);

    float* ybase = g_y + (size_t)b * TT * DD;

    // prefetch step-0 gathers
    float wx_n = 0.f, gg_n = 0.f;
    if (q == 0) {
        const int tok0 = stok[0];
        wx_n = __ldg(&g_EWx[tok0 * DD + eg]);
        gg_n = __ldg(&g_G[tok0 * DD + eg]);
    }

    int p = 0;

    for (int t = 0; t < TT; t++) {
        const float wx = wx_n, gg = gg_n;
        if (q == 0 && t + 1 < TT) {
            const int tokn = stok[t + 1];
            wx_n = __ldg(&g_EWx[tokn * DD + eg]);
            gg_n = __ldg(&g_G[tokn * DD + eg]);
        }

        // ---- phase A: local-half dot (hloc[p], barrier-ordered last step) ----
        unsigned long long acc_a = 0ull, acc_b = 0ull;
        {
            const ulonglong2* hb = (const ulonglong2*)(&hloc[p][36 * q]);
#pragma unroll
            for (int i = 0; i < 8; i++) {
                ulonglong2 h2 = hb[i];
                FFMA2(acc_a, wL[2 * i],     h2.x);
                FFMA2(acc_b, wL[2 * i + 1], h2.y);
            }
        }
        const float sA = f32x2_hsum4(acc_a, acc_b);

        // ---- phase B: poll-by-computing on peer half (NaN sentinel gate) ----
        float sB;
        {
            const uint32_t pa = pollAddr[p];
            unsigned long long hv[16], ba, bb;
            while (true) {
#pragma unroll
                for (int i = 0; i < 8; i++) {
                    asm volatile("ld.volatile.shared.v2.u64 {%0, %1}, [%2];"
                                 : "=l"(hv[2 * i]), "=l"(hv[2 * i + 1])
                                 : "r"(pa + 16 * i));
                }
                ba = 0ull; bb = 0ull;
#pragma unroll
                for (int i = 0; i < 8; i++) {
                    FFMA2(ba, wR[2 * i],     hv[2 * i]);
                    FFMA2(bb, wR[2 * i + 1], hv[2 * i + 1]);
                }
                sB = f32x2_hsum4(ba, bb);
                if (!__isnanf(sB)) break;   // any sentinel -> NaN -> retry
            }
        }

        float acc = sA + sB;
        acc += __shfl_xor_sync(0xffffffffu, acc, 1);
        acc += __shfl_xor_sync(0xffffffffu, acc, 2);

        const int np = p ^ 1;
        const bool last = (t == TT - 1);
        if (q == 0) {
            const float hn = tanh_fast(acc + wx);
            if (!last) {
                // publish to peer ASAP (plain weak DSMEM store; value IS the flag)
                asm volatile("st.shared::cluster.f32 [%0], %1;"
                             :: "r"(rhrem[np]), "f"(hn) : "memory");
            }
            hloc[np][jp] = hn;
            ybase[(size_t)t * DD + eg] = hn * gg;
        }

        __syncthreads();   // all phase-B reads of hrem[p] complete

        if (q == 1) ((volatile unsigned int*)hrem[p])[jp] = QNAN_U;  // re-arm

        __syncthreads();   // re-arm + hloc[np] writes ordered before next step
        p = np;
    }

    // exit safety: no CTA may leave while peer-directed traffic is in flight
    asm volatile("barrier.cluster.arrive.aligned;" ::: "memory");
    asm volatile("barrier.cluster.wait.aligned;"   ::: "memory");
}

// ================= Kernel 3: head GEMM =================
// logits[r][v] = sum_d y[r][d] * E[v][d].
// 64x64 tile per CTA, 4x4 micro-tile per thread, f32x2 pairs along k.
#define HKS 68   // 64 + 4 pad

__global__ __launch_bounds__(256) void head_kernel(
    const float* __restrict__ E,
    float* __restrict__ out)
{
    __shared__ __align__(16) float ys[64 * HKS];
    __shared__ __align__(16) float es[64 * HKS];

    const int tid = threadIdx.x;
    const int tx  = tid & 15;     // v-lane: cols tx, tx+16, tx+32, tx+48
    const int ty  = tid >> 4;     // row group: rows ty*4 .. ty*4+3
    const size_t rowbase = (size_t)(blockIdx.x >> 2) * 64;
    const int vbase = (blockIdx.x & 3) * 64;

    unsigned long long acc[4][4];
#pragma unroll
    for (int r = 0; r < 4; r++)
#pragma unroll
        for (int c = 0; c < 4; c++) acc[r][c] = 0ull;

    for (int kc = 0; kc < 4; kc++) {
        const int k0 = kc * 64;
        for (int i = tid; i < 1024; i += 256) {
            const int m = i >> 4, kk = i & 15;
            *(float4*)(ys + m * HKS + kk * 4) =
                *(const float4*)(g_y + (rowbase + m) * DD + k0 + kk * 4);
            *(float4*)(es + m * HKS + kk * 4) =
                *(const float4*)(E + (size_t)(vbase + m) * DD + k0 + kk * 4);
        }
        __syncthreads();

#pragma unroll
        for (int k4 = 0; k4 < 16; k4++) {
            ulonglong2 yv[4], ev[4];
#pragma unroll
            for (int r = 0; r < 4; r++)
                yv[r] = *(const ulonglong2*)(ys + (ty * 4 + r) * HKS + k4 * 4);
#pragma unroll
            for (int c = 0; c < 4; c++)
                ev[c] = *(const ulonglong2*)(es + (tx + 16 * c) * HKS + k4 * 4);
#pragma unroll
            for (int r = 0; r < 4; r++)
#pragma unroll
                for (int c = 0; c < 4; c++) {
                    FFMA2(acc[r][c], yv[r].x, ev[c].x);
                    FFMA2(acc[r][c], yv[r].y, ev[c].y);
                }
        }
        __syncthreads();
    }

#pragma unroll
    for (int r = 0; r < 4; r++) {
        float* orow = out + (rowbase + ty * 4 + r) * VV + vbase;
#pragma unroll
        for (int c = 0; c < 4; c++) {
            float lo, hi;
            asm("mov.b64 {%0, %1}, %2;" : "=f"(lo), "=f"(hi) : "l"(acc[r][c]));
            orow[tx + 16 * c] = lo + hi;
        }
    }
}

// ================= launch =================
extern "C" void kernel_launch(void* const* d_in, const int* in_sizes, int n_in,
                              void* d_out, int out_size)
{
    const int*   tokens = (const int*)  d_in[0];
    const float* E      = (const float*)d_in[1];
    const float* Wx     = (const float*)d_in[2];
    const float* Wh     = (const float*)d_in[3];
    const float* Wz     = (const float*)d_in[4];
    float* out = (float*)d_out;

    proj_kernel<<<VV, 256>>>(E, Wx, Wz);
    rnn_kernel<<<BB * 2, 512>>>(tokens, Wh);
    head_kernel<<<(BB * TT / 64) * (VV / 64), 256>>>(E, out);
}